// round 11
// baseline (speedup 1.0000x reference)
#include <cuda_runtime.h>
#include <cstdint>

#define BATCH 8192
#define NV    1000
#define CHEBK 5
#define NF    5
#define HIDD  256
#define NOUT  10
#define POOLD 625
#define MAXW  32
#define BT    8
#define HBT   4
#define NSLOT 1024
#define NGRP32 (NSLOT / 32)         // 32 warp-groups
#define STEPS 40
#define PLANE (NV * HBT)            // floats per half-plane (4000)

// ---------------- scratch ----------------
__device__ int2  g_ell[NV * MAXW];
__device__ int   g_ell_len[NV];
__device__ int   g_perm[NV];
__device__ int2  g_sched[NGRP32 * STEPS * 32];  // [grp][step][lane]
__device__ int   g_octlen[NGRP32 * 4];          // schedule length per octet
__device__ float g_pool[(size_t)BATCH * POOLD];
__device__ float g_z1[(size_t)BATCH * HIDD];
__device__ float g_z2[(size_t)BATCH * HIDD];

// ---------------- kernel 1: build ELL of Lr = 2*L/lmax - I (warp/row) ----------------
__global__ void build_ell(const float* __restrict__ L, const float* __restrict__ lmax) {
    const int warp = (blockIdx.x * blockDim.x + threadIdx.x) >> 5;
    const int lane = threadIdx.x & 31;
    if (warp >= NV) return;
    const int v = warp;
    const float inv = 2.0f / lmax[0];
    int cnt = 0;
    #pragma unroll 4
    for (int c = 0; c < (NV + 31) / 32; ++c) {
        const int u = c * 32 + lane;
        float val = 0.0f;
        if (u < NV) val = L[(size_t)v * NV + u] * inv - (u == v ? 1.0f : 0.0f);
        const bool nz = (val != 0.0f);
        const unsigned m = __ballot_sync(0xffffffffu, nz);
        if (nz) {
            const int idx = cnt + __popc(m & ((1u << lane) - 1u));
            if (idx < MAXW) g_ell[v * MAXW + idx] = make_int2(u, __float_as_int(val));
        }
        cnt += __popc(m);
    }
    if (lane == 0) g_ell_len[v] = cnt < MAXW ? cnt : MAXW;
}

// ---------------- kernel 1b: deterministic rank sort (lens staged in smem) ------------
// rank(v) = #{u : len[u] < len[v] or (equal and u < v)}; smem broadcast scan, ~2us.
__global__ void sort_nodes() {
    __shared__ int sl[NV];
    const int tid = threadIdx.x;
    if (tid < NV) sl[tid] = g_ell_len[tid];
    __syncthreads();
    if (tid < NV) {
        const int len = sl[tid];
        int pos = 0;
        for (int u = 0; u < NV; ++u) {
            const int lu = sl[u];
            pos += (lu < len) || (lu == len && u < tid);
        }
        g_perm[pos] = tid;
    }
}

// ---------------- kernel 1c: per-octet conflict-free gather schedule ----------------
// LDS.128 = 4 quarter-warp phases of 8 lanes; per-phase cost = max occupancy over the
// 8 position classes (v & 7). Greedy first-fit: each edge gets the earliest step that
// is free for its lane AND its class within the octet. Unfilled (step,lane) cells are
// padded with weight-0 entries on classes unused at that step -> fully conflict-free.
__global__ void schedule_ell() {
    const int oct = threadIdx.x;
    if (oct >= NGRP32 * 4) return;
    const int grp = oct >> 2, o = oct & 3;

    unsigned long long lanemask[8];   // steps occupied per lane
    unsigned long long clsmask[8];    // steps occupied per class
    #pragma unroll
    for (int i = 0; i < 8; ++i) { lanemask[i] = 0ull; clsmask[i] = 0ull; }

    int octlen = 0;
    for (int i = 0; i < 8; ++i) {
        const int slot = grp * 32 + o * 8 + i;
        if (slot >= NV) continue;
        const int v = g_perm[slot];
        const int len = g_ell_len[v];
        for (int j = 0; j < len; ++j) {
            const int2 e = g_ell[v * MAXW + j];
            const int c = e.x & 7;
            const unsigned long long freemask = ~(lanemask[i] | clsmask[c]);
            int t = (freemask != 0ull) ? __ffsll((long long)freemask) - 1 : STEPS;
            if (t >= STEPS) {   // fallback: lane-free only (always exists, len<=32<STEPS)
                t = __ffsll((long long)~lanemask[i]) - 1;
            }
            lanemask[i] |= 1ull << t;
            clsmask[c]  |= 1ull << t;
            g_sched[(grp * STEPS + t) * 32 + (o * 8 + i)] = e;
            if (t + 1 > octlen) octlen = t + 1;
        }
    }
    // pads: every remaining (step, lane) cell gets a weight-0 edge on a free class
    for (int t = 0; t < STEPS; ++t) {
        unsigned used = 0;
        #pragma unroll
        for (int c = 0; c < 8; ++c) used |= (unsigned)((clsmask[c] >> t) & 1ull) << c;
        for (int i = 0; i < 8; ++i) {
            if (!((lanemask[i] >> t) & 1ull)) {
                const int c = __ffs(~used) - 1;   // free class (<=8 cells => exists)
                used |= 1u << c;
                g_sched[(grp * STEPS + t) * 32 + (o * 8 + i)] = make_int2(c, 0);
            }
        }
    }
    g_octlen[oct] = octlen;
}

// ---------------- kernel 2: fused cheby + cl1 + relu + maxpool ----------------
__global__ __launch_bounds__(1024, 1)
void cheby_fused(const float* __restrict__ x,
                 const float* __restrict__ W,
                 const float* __restrict__ bias) {
    extern __shared__ float sT[];            // Lo[5][4000], Hi[5][4000], W/b[32]
    float* sLo = sT;
    float* sHi = sT + CHEBK * PLANE;
    float* sW  = sT + 2 * CHEBK * PLANE;
    const int b0  = blockIdx.x * BT;
    const int tid = threadIdx.x;

    if (tid < NF * CHEBK) sW[tid] = W[tid];
    if (tid < NF) sW[NF * CHEBK + tid] = bias[tid];

    // T0: lo half bb=0..3, hi half bb=4..7  (coalesced in v)
    #pragma unroll
    for (int i = tid; i < NV * BT; i += 1024) {
        const int bb = i / NV, v = i - bb * NV;
        const float val = x[(size_t)(b0 + bb) * NV + v];
        if (bb < HBT) sLo[v * HBT + bb] = val;
        else          sHi[v * HBT + (bb - HBT)] = val;
    }
    __syncthreads();

    const int slot = tid;
    const int grp  = tid >> 5, lane = tid & 31;
    int v = 0;
    if (slot < NV) v = g_perm[slot];
    // warp loop bound = max schedule length over the warp's 4 octets
    int lm = g_octlen[grp * 4 + 0];
    lm = max(lm, g_octlen[grp * 4 + 1]);
    lm = max(lm, g_octlen[grp * 4 + 2]);
    lm = max(lm, g_octlen[grp * 4 + 3]);
    const int2* __restrict__ ep = g_sched + grp * (STEPS * 32) + lane;

    #pragma unroll
    for (int k = 1; k < CHEBK; ++k) {
        const float* __restrict__ Lo1 = sLo + (k - 1) * PLANE;
        const float* __restrict__ Hi1 = sHi + (k - 1) * PLANE;
        float4 A0 = make_float4(0.f, 0.f, 0.f, 0.f);
        float4 A1 = make_float4(0.f, 0.f, 0.f, 0.f);
        #pragma unroll 2
        for (int j = 0; j < lm; ++j) {
            const int2 e = __ldg(&ep[j * 32]);       // coalesced 256B/warp
            const float w = __int_as_float(e.y);
            const float4 t0 = *reinterpret_cast<const float4*>(Lo1 + e.x * HBT);
            const float4 t1 = *reinterpret_cast<const float4*>(Hi1 + e.x * HBT);
            A0.x = fmaf(w, t0.x, A0.x); A0.y = fmaf(w, t0.y, A0.y);
            A0.z = fmaf(w, t0.z, A0.z); A0.w = fmaf(w, t0.w, A0.w);
            A1.x = fmaf(w, t1.x, A1.x); A1.y = fmaf(w, t1.y, A1.y);
            A1.z = fmaf(w, t1.z, A1.z); A1.w = fmaf(w, t1.w, A1.w);
        }
        if (slot < NV) {
            float4* toL = reinterpret_cast<float4*>(sLo + k * PLANE + v * HBT);
            float4* toH = reinterpret_cast<float4*>(sHi + k * PLANE + v * HBT);
            if (k == 1) {
                *toL = A0; *toH = A1;
            } else {
                const float4 ma = *reinterpret_cast<const float4*>(sLo + (k - 2) * PLANE + v * HBT);
                const float4 mb = *reinterpret_cast<const float4*>(sHi + (k - 2) * PLANE + v * HBT);
                *toL = make_float4(2.f * A0.x - ma.x, 2.f * A0.y - ma.y,
                                   2.f * A0.z - ma.z, 2.f * A0.w - ma.w);
                *toH = make_float4(2.f * A1.x - mb.x, 2.f * A1.y - mb.y,
                                   2.f * A1.z - mb.z, 2.f * A1.w - mb.w);
            }
        }
        __syncthreads();
    }

    // epilogue: 125 pool-groups * 8 bb = 1000 items
    if (tid < 125 * BT) {
        const int bb = tid & (BT - 1);
        const int g  = tid / BT;
        const float* base = (bb < HBT) ? sLo : sHi;
        const int bo = bb & (HBT - 1);
        float m[NF];
        #pragma unroll
        for (int f = 0; f < NF; ++f) m[f] = -3.4e38f;
        #pragma unroll
        for (int vi = 0; vi < 8; ++vi) {
            const int vv = g * 8 + vi;
            float t[CHEBK];
            #pragma unroll
            for (int k = 0; k < CHEBK; ++k) t[k] = base[k * PLANE + vv * HBT + bo];
            #pragma unroll
            for (int f = 0; f < NF; ++f) {
                float s = sW[NF * CHEBK + f];
                #pragma unroll
                for (int k = 0; k < CHEBK; ++k) s = fmaf(sW[f * CHEBK + k], t[k], s);
                m[f] = fmaxf(m[f], s);
            }
        }
        float* op = g_pool + (size_t)(b0 + bb) * POOLD + g * NF;
        #pragma unroll
        for (int f = 0; f < NF; ++f) op[f] = fmaxf(m[f], 0.0f);
    }
}

// ---------------- kernels 3/4: SGEMM C = A @ Bw^T + fused epilogue (unchanged) ---------
#define BM 128
#define BN 64
#define BKg 16

template <int EPI>
__global__ __launch_bounds__(256, 3)
void gemm_nt(const float* __restrict__ A, const float* __restrict__ Bw,
             const float* __restrict__ bias,
             const float* __restrict__ bn_gamma, const float* __restrict__ bn_beta,
             const float* __restrict__ bn_mean,  const float* __restrict__ bn_var,
             float* __restrict__ C, int Kd, int N) {
    __shared__ float As[2][BKg][BM + 4];
    __shared__ float Bs[2][BKg][BN + 4];

    const int tid  = threadIdx.x;
    const int tx   = tid & 15;
    const int ty   = tid >> 4;
    const int row0 = blockIdx.y * BM;
    const int col0 = blockIdx.x * BN;

    float acc[8][4];
    #pragma unroll
    for (int i = 0; i < 8; ++i)
        #pragma unroll
        for (int j = 0; j < 4; ++j) acc[i][j] = 0.0f;

    const int ntiles = (Kd + BKg - 1) / BKg;

    float ra[8], rb[4];
    auto load_tile = [&](int kt) {
        #pragma unroll
        for (int i = 0; i < 8; ++i) {
            const int idx = tid + i * 256;
            const int mm = idx >> 4, kk = idx & 15;
            const int kg = kt + kk;
            ra[i] = (kg < Kd) ? A[(size_t)(row0 + mm) * Kd + kg] : 0.0f;
        }
        #pragma unroll
        for (int i = 0; i < 4; ++i) {
            const int idx = tid + i * 256;
            const int mm = idx >> 4, kk = idx & 15;
            const int kg = kt + kk;
            rb[i] = (kg < Kd) ? Bw[(size_t)(col0 + mm) * Kd + kg] : 0.0f;
        }
    };
    auto store_tile = [&](int p) {
        #pragma unroll
        for (int i = 0; i < 8; ++i) {
            const int idx = tid + i * 256;
            As[p][idx & 15][idx >> 4] = ra[i];
        }
        #pragma unroll
        for (int i = 0; i < 4; ++i) {
            const int idx = tid + i * 256;
            Bs[p][idx & 15][idx >> 4] = rb[i];
        }
    };

    load_tile(0);
    store_tile(0);
    __syncthreads();

    int p = 0;
    for (int t = 0; t < ntiles; ++t) {
        if (t + 1 < ntiles) load_tile((t + 1) * BKg);
        #pragma unroll
        for (int kk = 0; kk < BKg; ++kk) {
            const float4* ap = reinterpret_cast<const float4*>(&As[p][kk][ty * 8]);
            const float4  a0 = ap[0], a1 = ap[1];
            const float4  b0 = *reinterpret_cast<const float4*>(&Bs[p][kk][tx * 4]);
            const float a[8] = {a0.x, a0.y, a0.z, a0.w, a1.x, a1.y, a1.z, a1.w};
            const float b[4] = {b0.x, b0.y, b0.z, b0.w};
            #pragma unroll
            for (int i = 0; i < 8; ++i)
                #pragma unroll
                for (int j = 0; j < 4; ++j) acc[i][j] = fmaf(a[i], b[j], acc[i][j]);
        }
        if (t + 1 < ntiles) {
            __syncthreads();
            store_tile(p ^ 1);
            __syncthreads();
        }
        p ^= 1;
    }

    float cb[4], cs[4][4], ct[4][4];
    #pragma unroll
    for (int j = 0; j < 4; ++j) {
        const int col = col0 + tx * 4 + j;
        cb[j] = __ldg(bias + col);
        if (EPI == 0) {
            #pragma unroll
            for (int l = 0; l < 4; ++l) {
                const int idx = l * HIDD + col;
                const float s = __ldg(bn_gamma + idx) * rsqrtf(__ldg(bn_var + idx) + 1e-5f);
                cs[j][l] = s;
                ct[j][l] = __ldg(bn_beta + idx) - __ldg(bn_mean + idx) * s;
            }
        }
    }

    #pragma unroll
    for (int i = 0; i < 8; ++i) {
        const int row = row0 + ty * 8 + i;
        float4 o;
        float* ov = &o.x;
        #pragma unroll
        for (int j = 0; j < 4; ++j) {
            float y = acc[i][j] + cb[j];
            if (EPI == 0) {
                float z = 0.0f;
                #pragma unroll
                for (int l = 0; l < 4; ++l) {
                    y = fmaxf(fmaf(y, cs[j][l], ct[j][l]), 0.0f);
                    z = fmaxf(z, y);
                }
                ov[j] = z;
            } else {
                ov[j] = fmaxf(y, 0.0f);
            }
        }
        *reinterpret_cast<float4*>(&C[(size_t)row * N + col0 + tx * 4]) = o;
    }
}

// ---------------- kernel 5: lin2 + log_softmax ----------------
__global__ void lin2_lsm(const float* __restrict__ Z2, const float* __restrict__ W2,
                         const float* __restrict__ b2, float* __restrict__ out) {
    const int gw   = (blockIdx.x * blockDim.x + threadIdx.x) >> 5;
    const int lane = threadIdx.x & 31;
    if (gw >= BATCH) return;
    const float* zr = Z2 + (size_t)gw * HIDD;
    float z[8];
    #pragma unroll
    for (int j = 0; j < 8; ++j) z[j] = zr[lane + 32 * j];

    float logit[NOUT];
    #pragma unroll
    for (int o = 0; o < NOUT; ++o) {
        float p = 0.0f;
        #pragma unroll
        for (int j = 0; j < 8; ++j) p += z[j] * __ldg(W2 + o * HIDD + lane + 32 * j);
        #pragma unroll
        for (int off = 16; off; off >>= 1) p += __shfl_xor_sync(0xffffffffu, p, off);
        logit[o] = p + __ldg(b2 + o);
    }
    float m = logit[0];
    #pragma unroll
    for (int o = 1; o < NOUT; ++o) m = fmaxf(m, logit[o]);
    float s = 0.0f;
    #pragma unroll
    for (int o = 0; o < NOUT; ++o) s += expf(logit[o] - m);
    const float lse = m + logf(s);
    if (lane < NOUT) out[(size_t)gw * NOUT + lane] = logit[lane] - lse;
}

// ---------------- launcher ----------------
extern "C" void kernel_launch(void* const* d_in, const int* in_sizes, int n_in,
                              void* d_out, int out_size) {
    const float* x        = (const float*)d_in[0];
    const float* L        = (const float*)d_in[1];
    const float* lmax     = (const float*)d_in[2];
    const float* cl1W     = (const float*)d_in[3];
    const float* cl1b     = (const float*)d_in[4];
    const float* fc1W     = (const float*)d_in[5];
    const float* fc1b     = (const float*)d_in[6];
    const float* bn_gamma = (const float*)d_in[7];
    const float* bn_beta  = (const float*)d_in[8];
    const float* bn_mean  = (const float*)d_in[9];
    const float* bn_var   = (const float*)d_in[10];
    const float* lin1W    = (const float*)d_in[11];
    const float* lin1b    = (const float*)d_in[12];
    const float* lin2W    = (const float*)d_in[13];
    const float* lin2b    = (const float*)d_in[14];
    float* out = (float*)d_out;

    float *pPool, *pZ1, *pZ2;
    cudaGetSymbolAddress((void**)&pPool, g_pool);
    cudaGetSymbolAddress((void**)&pZ1,  g_z1);
    cudaGetSymbolAddress((void**)&pZ2,  g_z2);

    // 1) sparse extraction + smem rank sort + conflict-free gather schedule
    build_ell<<<(NV * 32 + 255) / 256, 256>>>(L, lmax);
    sort_nodes<<<1, 1024>>>();
    schedule_ell<<<1, NGRP32 * 4>>>();

    // 2) fused chebyshev + cl1 + relu + maxpool (scheduled conflict-free gathers)
    const int smem = (2 * CHEBK * PLANE + 32) * (int)sizeof(float);  // 160128 B
    cudaFuncSetAttribute(cheby_fused, cudaFuncAttributeMaxDynamicSharedMemorySize, smem);
    cheby_fused<<<BATCH / BT, 1024, smem>>>(x, cl1W, cl1b);

    // 3) fc1 + BN x4 + relu + JK-max  (M=8192, N=256, K=625)
    dim3 grid(HIDD / BN, BATCH / BM);   // (4, 64) = 256 CTAs
    gemm_nt<0><<<grid, 256>>>(pPool, fc1W, fc1b, bn_gamma, bn_beta, bn_mean, bn_var,
                              pZ1, POOLD, HIDD);

    // 4) lin1 + relu  (M=8192, N=256, K=256)
    gemm_nt<1><<<grid, 256>>>(pZ1, lin1W, lin1b, nullptr, nullptr, nullptr, nullptr,
                              pZ2, HIDD, HIDD);

    // 5) lin2 + log_softmax
    lin2_lsm<<<BATCH / 8, 256>>>(pZ2, lin2W, lin2b, out);
}

// round 12
// speedup vs baseline: 1.7688x; 1.7688x over previous
#include <cuda_runtime.h>
#include <cstdint>

#define BATCH 8192
#define NV    1000
#define CHEBK 5
#define NF    5
#define HIDD  256
#define NOUT  10
#define POOLD 625
#define MAXW  32
#define BT    8
#define HBT   4
#define NSLOT 1024
#define PLANE (NV * HBT)            // floats per half-plane (4000)

// ---------------- scratch ----------------
__device__ int2  g_ell[NV * MAXW];
__device__ int   g_ell_len[NV];
__device__ int   g_perm[NV];
__device__ int2  g_ellT[(NSLOT / 32) * MAXW * 32];  // lane-major [grp][j][lane]
__device__ float g_pool[(size_t)BATCH * POOLD];
__device__ float g_z1[(size_t)BATCH * HIDD];
__device__ float g_z2[(size_t)BATCH * HIDD];

// ---------------- kernel 1: build ELL of Lr = 2*L/lmax - I (warp/row) ----------------
__global__ void build_ell(const float* __restrict__ L, const float* __restrict__ lmax) {
    const int warp = (blockIdx.x * blockDim.x + threadIdx.x) >> 5;
    const int lane = threadIdx.x & 31;
    if (warp >= NV) return;
    const int v = warp;
    const float inv = 2.0f / lmax[0];
    int cnt = 0;
    #pragma unroll 4
    for (int c = 0; c < (NV + 31) / 32; ++c) {
        const int u = c * 32 + lane;
        float val = 0.0f;
        if (u < NV) val = L[(size_t)v * NV + u] * inv - (u == v ? 1.0f : 0.0f);
        const bool nz = (val != 0.0f);
        const unsigned m = __ballot_sync(0xffffffffu, nz);
        if (nz) {
            const int idx = cnt + __popc(m & ((1u << lane) - 1u));
            if (idx < MAXW) g_ell[v * MAXW + idx] = make_int2(u, __float_as_int(val));
        }
        cnt += __popc(m);
    }
    if (lane == 0) g_ell_len[v] = cnt < MAXW ? cnt : MAXW;
}

// ---------------- kernel 1b: deterministic rank sort (lens staged in smem) ------------
// rank(v) = #{u : len[u] < len[v] or (equal and u < v)}; smem broadcast scan.
__global__ void sort_nodes() {
    __shared__ int sl[NV];
    const int tid = threadIdx.x;
    if (tid < NV) sl[tid] = g_ell_len[tid];
    __syncthreads();
    if (tid < NV) {
        const int len = sl[tid];
        int pos = 0;
        for (int u = 0; u < NV; ++u) {
            const int lu = sl[u];
            pos += (lu < len) || (lu == len && u < tid);
        }
        g_perm[pos] = tid;
    }
}

// ---------------- kernel 1c: lane-major transpose with class-rotation sort ------------
// Bank-position class of a gather = e.x & 7 (node stride 16B in the half-planes).
// Each lane sorts its edges by ((class - (lane&7)) & 7): the 32 lanes of a compute
// warp start 4-per-class and stay roughly coordinated (measured ~5% cheby win).
__global__ void transpose_ell() {
    const int s = blockIdx.x * blockDim.x + threadIdx.x;
    if (s >= NSLOT) return;
    const int grp = s >> 5, lane = s & 31;
    const int r = lane & 7;
    int v = -1, len = 0;
    if (s < NV) { v = g_perm[s]; len = g_ell_len[v]; }

    int2 e[MAXW];
    for (int j = 0; j < len; ++j) e[j] = g_ell[v * MAXW + j];
    // stable insertion sort by rotated class (deterministic)
    for (int i = 1; i < len; ++i) {
        const int2 key = e[i];
        const int kc = ((key.x & 7) - r) & 7;
        int j = i - 1;
        while (j >= 0 && ((((e[j].x & 7) - r) & 7) > kc)) { e[j + 1] = e[j]; --j; }
        e[j + 1] = key;
    }
    int2* dst = g_ellT + grp * (MAXW * 32) + lane;
    for (int j = 0; j < MAXW; ++j)
        dst[j * 32] = (j < len) ? e[j] : make_int2(0, 0);
}

// ---------------- kernel 2: fused cheby + cl1 + relu + maxpool (R10 shape) ------------
__global__ __launch_bounds__(1024, 1)
void cheby_fused(const float* __restrict__ x,
                 const float* __restrict__ W,
                 const float* __restrict__ bias) {
    extern __shared__ float sT[];            // Lo[5][4000], Hi[5][4000], W/b[32]
    float* sLo = sT;
    float* sHi = sT + CHEBK * PLANE;
    float* sW  = sT + 2 * CHEBK * PLANE;
    const int b0  = blockIdx.x * BT;
    const int tid = threadIdx.x;

    if (tid < NF * CHEBK) sW[tid] = W[tid];
    if (tid < NF) sW[NF * CHEBK + tid] = bias[tid];

    // T0: lo half bb=0..3, hi half bb=4..7  (coalesced in v)
    #pragma unroll
    for (int i = tid; i < NV * BT; i += 1024) {
        const int bb = i / NV, v = i - bb * NV;
        const float val = x[(size_t)(b0 + bb) * NV + v];
        if (bb < HBT) sLo[v * HBT + bb] = val;
        else          sHi[v * HBT + (bb - HBT)] = val;
    }
    __syncthreads();

    const int slot = tid;
    const int grp  = tid >> 5, lane = tid & 31;
    int v = 0, len = 0;
    if (slot < NV) { v = g_perm[slot]; len = g_ell_len[v]; }
    const int lm = __reduce_max_sync(0xffffffffu, len);
    const int2* __restrict__ ep = g_ellT + grp * (MAXW * 32) + lane;

    #pragma unroll
    for (int k = 1; k < CHEBK; ++k) {
        const float* __restrict__ Lo1 = sLo + (k - 1) * PLANE;
        const float* __restrict__ Hi1 = sHi + (k - 1) * PLANE;
        float4 A0 = make_float4(0.f, 0.f, 0.f, 0.f);
        float4 A1 = make_float4(0.f, 0.f, 0.f, 0.f);
        #pragma unroll 2
        for (int j = 0; j < lm; ++j) {
            const int2 e = __ldg(&ep[j * 32]);       // coalesced 256B/warp
            const float w = __int_as_float(e.y);
            const float4 t0 = *reinterpret_cast<const float4*>(Lo1 + e.x * HBT);
            const float4 t1 = *reinterpret_cast<const float4*>(Hi1 + e.x * HBT);
            A0.x = fmaf(w, t0.x, A0.x); A0.y = fmaf(w, t0.y, A0.y);
            A0.z = fmaf(w, t0.z, A0.z); A0.w = fmaf(w, t0.w, A0.w);
            A1.x = fmaf(w, t1.x, A1.x); A1.y = fmaf(w, t1.y, A1.y);
            A1.z = fmaf(w, t1.z, A1.z); A1.w = fmaf(w, t1.w, A1.w);
        }
        if (slot < NV) {
            float4* toL = reinterpret_cast<float4*>(sLo + k * PLANE + v * HBT);
            float4* toH = reinterpret_cast<float4*>(sHi + k * PLANE + v * HBT);
            if (k == 1) {
                *toL = A0; *toH = A1;
            } else {
                const float4 ma = *reinterpret_cast<const float4*>(sLo + (k - 2) * PLANE + v * HBT);
                const float4 mb = *reinterpret_cast<const float4*>(sHi + (k - 2) * PLANE + v * HBT);
                *toL = make_float4(2.f * A0.x - ma.x, 2.f * A0.y - ma.y,
                                   2.f * A0.z - ma.z, 2.f * A0.w - ma.w);
                *toH = make_float4(2.f * A1.x - mb.x, 2.f * A1.y - mb.y,
                                   2.f * A1.z - mb.z, 2.f * A1.w - mb.w);
            }
        }
        __syncthreads();
    }

    // epilogue: 125 pool-groups * 8 bb = 1000 items
    if (tid < 125 * BT) {
        const int bb = tid & (BT - 1);
        const int g  = tid / BT;
        const float* base = (bb < HBT) ? sLo : sHi;
        const int bo = bb & (HBT - 1);
        float m[NF];
        #pragma unroll
        for (int f = 0; f < NF; ++f) m[f] = -3.4e38f;
        #pragma unroll
        for (int vi = 0; vi < 8; ++vi) {
            const int vv = g * 8 + vi;
            float t[CHEBK];
            #pragma unroll
            for (int k = 0; k < CHEBK; ++k) t[k] = base[k * PLANE + vv * HBT + bo];
            #pragma unroll
            for (int f = 0; f < NF; ++f) {
                float s = sW[NF * CHEBK + f];
                #pragma unroll
                for (int k = 0; k < CHEBK; ++k) s = fmaf(sW[f * CHEBK + k], t[k], s);
                m[f] = fmaxf(m[f], s);
            }
        }
        float* op = g_pool + (size_t)(b0 + bb) * POOLD + g * NF;
        #pragma unroll
        for (int f = 0; f < NF; ++f) op[f] = fmaxf(m[f], 0.0f);
    }
}

// ---------------- kernels 3/4: SGEMM C = A @ Bw^T + fused epilogue (unchanged) ---------
#define BM 128
#define BN 64
#define BKg 16

template <int EPI>
__global__ __launch_bounds__(256, 3)
void gemm_nt(const float* __restrict__ A, const float* __restrict__ Bw,
             const float* __restrict__ bias,
             const float* __restrict__ bn_gamma, const float* __restrict__ bn_beta,
             const float* __restrict__ bn_mean,  const float* __restrict__ bn_var,
             float* __restrict__ C, int Kd, int N) {
    __shared__ float As[2][BKg][BM + 4];
    __shared__ float Bs[2][BKg][BN + 4];

    const int tid  = threadIdx.x;
    const int tx   = tid & 15;
    const int ty   = tid >> 4;
    const int row0 = blockIdx.y * BM;
    const int col0 = blockIdx.x * BN;

    float acc[8][4];
    #pragma unroll
    for (int i = 0; i < 8; ++i)
        #pragma unroll
        for (int j = 0; j < 4; ++j) acc[i][j] = 0.0f;

    const int ntiles = (Kd + BKg - 1) / BKg;

    float ra[8], rb[4];
    auto load_tile = [&](int kt) {
        #pragma unroll
        for (int i = 0; i < 8; ++i) {
            const int idx = tid + i * 256;
            const int mm = idx >> 4, kk = idx & 15;
            const int kg = kt + kk;
            ra[i] = (kg < Kd) ? A[(size_t)(row0 + mm) * Kd + kg] : 0.0f;
        }
        #pragma unroll
        for (int i = 0; i < 4; ++i) {
            const int idx = tid + i * 256;
            const int mm = idx >> 4, kk = idx & 15;
            const int kg = kt + kk;
            rb[i] = (kg < Kd) ? Bw[(size_t)(col0 + mm) * Kd + kg] : 0.0f;
        }
    };
    auto store_tile = [&](int p) {
        #pragma unroll
        for (int i = 0; i < 8; ++i) {
            const int idx = tid + i * 256;
            As[p][idx & 15][idx >> 4] = ra[i];
        }
        #pragma unroll
        for (int i = 0; i < 4; ++i) {
            const int idx = tid + i * 256;
            Bs[p][idx & 15][idx >> 4] = rb[i];
        }
    };

    load_tile(0);
    store_tile(0);
    __syncthreads();

    int p = 0;
    for (int t = 0; t < ntiles; ++t) {
        if (t + 1 < ntiles) load_tile((t + 1) * BKg);
        #pragma unroll
        for (int kk = 0; kk < BKg; ++kk) {
            const float4* ap = reinterpret_cast<const float4*>(&As[p][kk][ty * 8]);
            const float4  a0 = ap[0], a1 = ap[1];
            const float4  b0 = *reinterpret_cast<const float4*>(&Bs[p][kk][tx * 4]);
            const float a[8] = {a0.x, a0.y, a0.z, a0.w, a1.x, a1.y, a1.z, a1.w};
            const float b[4] = {b0.x, b0.y, b0.z, b0.w};
            #pragma unroll
            for (int i = 0; i < 8; ++i)
                #pragma unroll
                for (int j = 0; j < 4; ++j) acc[i][j] = fmaf(a[i], b[j], acc[i][j]);
        }
        if (t + 1 < ntiles) {
            __syncthreads();
            store_tile(p ^ 1);
            __syncthreads();
        }
        p ^= 1;
    }

    float cb[4], cs[4][4], ct[4][4];
    #pragma unroll
    for (int j = 0; j < 4; ++j) {
        const int col = col0 + tx * 4 + j;
        cb[j] = __ldg(bias + col);
        if (EPI == 0) {
            #pragma unroll
            for (int l = 0; l < 4; ++l) {
                const int idx = l * HIDD + col;
                const float s = __ldg(bn_gamma + idx) * rsqrtf(__ldg(bn_var + idx) + 1e-5f);
                cs[j][l] = s;
                ct[j][l] = __ldg(bn_beta + idx) - __ldg(bn_mean + idx) * s;
            }
        }
    }

    #pragma unroll
    for (int i = 0; i < 8; ++i) {
        const int row = row0 + ty * 8 + i;
        float4 o;
        float* ov = &o.x;
        #pragma unroll
        for (int j = 0; j < 4; ++j) {
            float y = acc[i][j] + cb[j];
            if (EPI == 0) {
                float z = 0.0f;
                #pragma unroll
                for (int l = 0; l < 4; ++l) {
                    y = fmaxf(fmaf(y, cs[j][l], ct[j][l]), 0.0f);
                    z = fmaxf(z, y);
                }
                ov[j] = z;
            } else {
                ov[j] = fmaxf(y, 0.0f);
            }
        }
        *reinterpret_cast<float4*>(&C[(size_t)row * N + col0 + tx * 4]) = o;
    }
}

// ---------------- kernel 5: lin2 + log_softmax ----------------
__global__ void lin2_lsm(const float* __restrict__ Z2, const float* __restrict__ W2,
                         const float* __restrict__ b2, float* __restrict__ out) {
    const int gw   = (blockIdx.x * blockDim.x + threadIdx.x) >> 5;
    const int lane = threadIdx.x & 31;
    if (gw >= BATCH) return;
    const float* zr = Z2 + (size_t)gw * HIDD;
    float z[8];
    #pragma unroll
    for (int j = 0; j < 8; ++j) z[j] = zr[lane + 32 * j];

    float logit[NOUT];
    #pragma unroll
    for (int o = 0; o < NOUT; ++o) {
        float p = 0.0f;
        #pragma unroll
        for (int j = 0; j < 8; ++j) p += z[j] * __ldg(W2 + o * HIDD + lane + 32 * j);
        #pragma unroll
        for (int off = 16; off; off >>= 1) p += __shfl_xor_sync(0xffffffffu, p, off);
        logit[o] = p + __ldg(b2 + o);
    }
    float m = logit[0];
    #pragma unroll
    for (int o = 1; o < NOUT; ++o) m = fmaxf(m, logit[o]);
    float s = 0.0f;
    #pragma unroll
    for (int o = 0; o < NOUT; ++o) s += expf(logit[o] - m);
    const float lse = m + logf(s);
    if (lane < NOUT) out[(size_t)gw * NOUT + lane] = logit[lane] - lse;
}

// ---------------- launcher ----------------
extern "C" void kernel_launch(void* const* d_in, const int* in_sizes, int n_in,
                              void* d_out, int out_size) {
    const float* x        = (const float*)d_in[0];
    const float* L        = (const float*)d_in[1];
    const float* lmax     = (const float*)d_in[2];
    const float* cl1W     = (const float*)d_in[3];
    const float* cl1b     = (const float*)d_in[4];
    const float* fc1W     = (const float*)d_in[5];
    const float* fc1b     = (const float*)d_in[6];
    const float* bn_gamma = (const float*)d_in[7];
    const float* bn_beta  = (const float*)d_in[8];
    const float* bn_mean  = (const float*)d_in[9];
    const float* bn_var   = (const float*)d_in[10];
    const float* lin1W    = (const float*)d_in[11];
    const float* lin1b    = (const float*)d_in[12];
    const float* lin2W    = (const float*)d_in[13];
    const float* lin2b    = (const float*)d_in[14];
    float* out = (float*)d_out;

    float *pPool, *pZ1, *pZ2;
    cudaGetSymbolAddress((void**)&pPool, g_pool);
    cudaGetSymbolAddress((void**)&pZ1,  g_z1);
    cudaGetSymbolAddress((void**)&pZ2,  g_z2);

    // 1) sparse extraction + fast smem rank sort + class-rotated transpose
    build_ell<<<(NV * 32 + 255) / 256, 256>>>(L, lmax);
    sort_nodes<<<1, 1024>>>();
    transpose_ell<<<NSLOT / 256, 256>>>();

    // 2) fused chebyshev + cl1 + relu + maxpool (split-half planes)
    const int smem = (2 * CHEBK * PLANE + 32) * (int)sizeof(float);  // 160128 B
    cudaFuncSetAttribute(cheby_fused, cudaFuncAttributeMaxDynamicSharedMemorySize, smem);
    cheby_fused<<<BATCH / BT, 1024, smem>>>(x, cl1W, cl1b);

    // 3) fc1 + BN x4 + relu + JK-max  (M=8192, N=256, K=625)
    dim3 grid(HIDD / BN, BATCH / BM);   // (4, 64) = 256 CTAs
    gemm_nt<0><<<grid, 256>>>(pPool, fc1W, fc1b, bn_gamma, bn_beta, bn_mean, bn_var,
                              pZ1, POOLD, HIDD);

    // 4) lin1 + relu  (M=8192, N=256, K=256)
    gemm_nt<1><<<grid, 256>>>(pZ1, lin1W, lin1b, nullptr, nullptr, nullptr, nullptr,
                              pZ2, HIDD, HIDD);

    // 5) lin2 + log_softmax
    lin2_lsm<<<BATCH / 8, 256>>>(pZ2, lin2W, lin2b, out);
}

// round 14
// speedup vs baseline: 2.0008x; 1.1311x over previous
#include <cuda_runtime.h>
#include <cuda_bf16.h>
#include <cstdint>

#define BATCH 8192
#define NV    1000
#define CHEBK 5
#define NF    5
#define HIDD  256
#define NOUT  10
#define KPAD  640
#define MAXW  32
#define BT    8
#define HBT   4
#define NSLOT 1024
#define PLANE (NV * HBT)

// ---------------- scratch ----------------
__device__ int2  g_ell[NV * MAXW];
__device__ int   g_ell_len[NV];
__device__ int   g_perm[NV];
__device__ int2  g_ellT[(NSLOT / 32) * MAXW * 32];
__device__ __nv_bfloat16 g_poolh[(size_t)BATCH * KPAD];   // pads (625..639) stay 0
__device__ __nv_bfloat16 g_pooll[(size_t)BATCH * KPAD];
__device__ __nv_bfloat16 g_fc1h[HIDD * KPAD];
__device__ __nv_bfloat16 g_fc1l[HIDD * KPAD];
__device__ __nv_bfloat16 g_lin1h[HIDD * HIDD];
__device__ __nv_bfloat16 g_lin1l[HIDD * HIDD];
__device__ __nv_bfloat16 g_z1h[(size_t)BATCH * HIDD];
__device__ __nv_bfloat16 g_z1l[(size_t)BATCH * HIDD];
__device__ float g_z2[(size_t)BATCH * HIDD];

// ---------------- helpers ----------------
__device__ __forceinline__ uint32_t smem_u32(const void* p) {
    uint32_t a;
    asm("{ .reg .u64 t; cvta.to.shared.u64 t, %1; cvt.u32.u64 %0, t; }" : "=r"(a) : "l"(p));
    return a;
}
__device__ __forceinline__ void bf16_split(float x, __nv_bfloat16& h, __nv_bfloat16& l) {
    h = __float2bfloat16(x);
    l = __float2bfloat16(x - __bfloat162float(h));
}
__device__ __forceinline__ void ldm_x4(uint32_t addr, uint32_t* r) {
    asm volatile("ldmatrix.sync.aligned.m8n8.x4.shared.b16 {%0,%1,%2,%3}, [%4];"
                 : "=r"(r[0]), "=r"(r[1]), "=r"(r[2]), "=r"(r[3]) : "r"(addr));
}
__device__ __forceinline__ void mma_bf16(float* d, const uint32_t* a, const uint32_t* b) {
    asm volatile("mma.sync.aligned.m16n8k16.row.col.f32.bf16.bf16.f32 "
                 "{%0,%1,%2,%3}, {%4,%5,%6,%7}, {%8,%9}, {%0,%1,%2,%3};"
                 : "+f"(d[0]), "+f"(d[1]), "+f"(d[2]), "+f"(d[3])
                 : "r"(a[0]), "r"(a[1]), "r"(a[2]), "r"(a[3]), "r"(b[0]), "r"(b[1]));
}

// ---------------- kernel 1: build ELL of Lr = 2*L/lmax - I (warp/row) ----------------
__global__ void build_ell(const float* __restrict__ L, const float* __restrict__ lmax) {
    const int warp = (blockIdx.x * blockDim.x + threadIdx.x) >> 5;
    const int lane = threadIdx.x & 31;
    if (warp >= NV) return;
    const int v = warp;
    const float inv = 2.0f / lmax[0];
    int cnt = 0;
    #pragma unroll 4
    for (int c = 0; c < (NV + 31) / 32; ++c) {
        const int u = c * 32 + lane;
        float val = 0.0f;
        if (u < NV) val = L[(size_t)v * NV + u] * inv - (u == v ? 1.0f : 0.0f);
        const bool nz = (val != 0.0f);
        const unsigned m = __ballot_sync(0xffffffffu, nz);
        if (nz) {
            const int idx = cnt + __popc(m & ((1u << lane) - 1u));
            if (idx < MAXW) g_ell[v * MAXW + idx] = make_int2(u, __float_as_int(val));
        }
        cnt += __popc(m);
    }
    if (lane == 0) g_ell_len[v] = cnt < MAXW ? cnt : MAXW;
}

// ---------------- kernel 1b: deterministic rank sort (smem staged) ----------------
__global__ void sort_nodes() {
    __shared__ int sl[NV];
    const int tid = threadIdx.x;
    if (tid < NV) sl[tid] = g_ell_len[tid];
    __syncthreads();
    if (tid < NV) {
        const int len = sl[tid];
        int pos = 0;
        for (int u = 0; u < NV; ++u) {
            const int lu = sl[u];
            pos += (lu < len) || (lu == len && u < tid);
        }
        g_perm[pos] = tid;
    }
}

// ---------------- kernel 1c: lane-major transpose, rotated-class order ----------------
// 8-pass class scan (no local arrays -> no spill). Deterministic.
__global__ void transpose_ell() {
    const int s = blockIdx.x * blockDim.x + threadIdx.x;
    if (s >= NSLOT) return;
    const int grp = s >> 5, lane = s & 31;
    const int r = lane & 7;
    int v = -1, len = 0;
    if (s < NV) { v = g_perm[s]; len = g_ell_len[v]; }
    int2* dst = g_ellT + grp * (MAXW * 32) + lane;
    int jo = 0;
    for (int cc = 0; cc < 8; ++cc) {
        for (int j = 0; j < len; ++j) {
            const int2 e = g_ell[v * MAXW + j];
            if ((((e.x & 7) - r) & 7) == cc) dst[(jo++) * 32] = e;
        }
    }
    for (; jo < MAXW; ++jo) dst[jo * 32] = make_int2(0, 0);
}

// ---------------- kernel 1d: weight conversion to bf16 hi/lo ----------------
__global__ void conv_weights(const float* __restrict__ fc1W, const float* __restrict__ lin1W) {
    const int i = blockIdx.x * blockDim.x + threadIdx.x;
    if (i < HIDD * 625) {
        const int n = i / 625, k = i - n * 625;
        __nv_bfloat16 h, l;
        bf16_split(fc1W[i], h, l);
        g_fc1h[n * KPAD + k] = h;
        g_fc1l[n * KPAD + k] = l;
    }
    if (i < HIDD * HIDD) {
        __nv_bfloat16 h, l;
        bf16_split(lin1W[i], h, l);
        g_lin1h[i] = h;
        g_lin1l[i] = l;
    }
}

// ---------------- kernel 2: fused cheby + cl1 + relu + maxpool -> bf16 hi/lo ----------
__global__ __launch_bounds__(1024, 1)
void cheby_fused(const float* __restrict__ x,
                 const float* __restrict__ W,
                 const float* __restrict__ bias) {
    extern __shared__ float sT[];            // Lo[5][4000], Hi[5][4000], W/b[32]
    float* sLo = sT;
    float* sHi = sT + CHEBK * PLANE;
    float* sW  = sT + 2 * CHEBK * PLANE;
    const int b0  = blockIdx.x * BT;
    const int tid = threadIdx.x;

    if (tid < NF * CHEBK) sW[tid] = W[tid];
    if (tid < NF) sW[NF * CHEBK + tid] = bias[tid];

    #pragma unroll
    for (int i = tid; i < NV * BT; i += 1024) {
        const int bb = i / NV, v = i - bb * NV;
        const float val = x[(size_t)(b0 + bb) * NV + v];
        if (bb < HBT) sLo[v * HBT + bb] = val;
        else          sHi[v * HBT + (bb - HBT)] = val;
    }
    __syncthreads();

    const int slot = tid;
    const int grp  = tid >> 5, lane = tid & 31;
    int v = 0, len = 0;
    if (slot < NV) { v = g_perm[slot]; len = g_ell_len[v]; }
    const int lm = __reduce_max_sync(0xffffffffu, len);
    const int2* __restrict__ ep = g_ellT + grp * (MAXW * 32) + lane;

    #pragma unroll
    for (int k = 1; k < CHEBK; ++k) {
        const float* __restrict__ Lo1 = sLo + (k - 1) * PLANE;
        const float* __restrict__ Hi1 = sHi + (k - 1) * PLANE;
        float4 A0 = make_float4(0.f, 0.f, 0.f, 0.f);
        float4 A1 = make_float4(0.f, 0.f, 0.f, 0.f);
        #pragma unroll 2
        for (int j = 0; j < lm; ++j) {
            const int2 e = __ldg(&ep[j * 32]);
            const float w = __int_as_float(e.y);
            const float4 t0 = *reinterpret_cast<const float4*>(Lo1 + e.x * HBT);
            const float4 t1 = *reinterpret_cast<const float4*>(Hi1 + e.x * HBT);
            A0.x = fmaf(w, t0.x, A0.x); A0.y = fmaf(w, t0.y, A0.y);
            A0.z = fmaf(w, t0.z, A0.z); A0.w = fmaf(w, t0.w, A0.w);
            A1.x = fmaf(w, t1.x, A1.x); A1.y = fmaf(w, t1.y, A1.y);
            A1.z = fmaf(w, t1.z, A1.z); A1.w = fmaf(w, t1.w, A1.w);
        }
        if (slot < NV) {
            float4* toL = reinterpret_cast<float4*>(sLo + k * PLANE + v * HBT);
            float4* toH = reinterpret_cast<float4*>(sHi + k * PLANE + v * HBT);
            if (k == 1) {
                *toL = A0; *toH = A1;
            } else {
                const float4 ma = *reinterpret_cast<const float4*>(sLo + (k - 2) * PLANE + v * HBT);
                const float4 mb = *reinterpret_cast<const float4*>(sHi + (k - 2) * PLANE + v * HBT);
                *toL = make_float4(2.f * A0.x - ma.x, 2.f * A0.y - ma.y,
                                   2.f * A0.z - ma.z, 2.f * A0.w - ma.w);
                *toH = make_float4(2.f * A1.x - mb.x, 2.f * A1.y - mb.y,
                                   2.f * A1.z - mb.z, 2.f * A1.w - mb.w);
            }
        }
        __syncthreads();
    }

    if (tid < 125 * BT) {
        const int bb = tid & (BT - 1);
        const int g  = tid / BT;
        const float* base = (bb < HBT) ? sLo : sHi;
        const int bo = bb & (HBT - 1);
        float m[NF];
        #pragma unroll
        for (int f = 0; f < NF; ++f) m[f] = -3.4e38f;
        #pragma unroll
        for (int vi = 0; vi < 8; ++vi) {
            const int vv = g * 8 + vi;
            float t[CHEBK];
            #pragma unroll
            for (int k = 0; k < CHEBK; ++k) t[k] = base[k * PLANE + vv * HBT + bo];
            #pragma unroll
            for (int f = 0; f < NF; ++f) {
                float s = sW[NF * CHEBK + f];
                #pragma unroll
                for (int k = 0; k < CHEBK; ++k) s = fmaf(sW[f * CHEBK + k], t[k], s);
                m[f] = fmaxf(m[f], s);
            }
        }
        const size_t op = (size_t)(b0 + bb) * KPAD + g * NF;
        #pragma unroll
        for (int f = 0; f < NF; ++f) {
            __nv_bfloat16 h, l;
            bf16_split(fmaxf(m[f], 0.0f), h, l);
            g_poolh[op + f] = h;
            g_pooll[op + f] = l;
        }
    }
}

// ---------------- kernels 3/4: mma.sync bf16-split GEMM  C = A @ B^T + epilogue -------
// CTA tile 128x64, 8 warps (4x2), warp tile 32x32 (2x4 m16n8k16 frags).
// 3 MMA passes per fragment: Ah*Bh + Al*Bh + Ah*Bl (lo*lo dropped, ~2^-18).
#define SSTR 40   // smem row stride in bf16 (32 + 8 pad): ldmatrix conflict-free

template <int EPI>
__global__ __launch_bounds__(256, 2)
void gemm_mma(const __nv_bfloat16* __restrict__ Ah, const __nv_bfloat16* __restrict__ Al,
              int lda,
              const __nv_bfloat16* __restrict__ Bh, const __nv_bfloat16* __restrict__ Bl,
              int ldb, int ktiles,
              const float* __restrict__ bias,
              const float* __restrict__ bn_gamma, const float* __restrict__ bn_beta,
              const float* __restrict__ bn_mean,  const float* __restrict__ bn_var,
              float* __restrict__ Cf,
              __nv_bfloat16* __restrict__ Ch, __nv_bfloat16* __restrict__ Cl, int ldc) {
    __shared__ __nv_bfloat16 sAH[128 * SSTR], sAL[128 * SSTR];
    __shared__ __nv_bfloat16 sBH[64 * SSTR],  sBL[64 * SSTR];

    const int tid = threadIdx.x, wid = tid >> 5, lane = tid & 31;
    const int wm = wid >> 1, wn = wid & 1;
    const int m0 = blockIdx.y * 128, n0 = blockIdx.x * 64;

    float acc[2][4][4];
    #pragma unroll
    for (int a = 0; a < 2; ++a)
        #pragma unroll
        for (int b = 0; b < 4; ++b)
            #pragma unroll
            for (int c = 0; c < 4; ++c) acc[a][b][c] = 0.0f;

    const uint32_t aBH = smem_u32(sAH), aBL = smem_u32(sAL);
    const uint32_t bBH = smem_u32(sBH), bBL = smem_u32(sBL);
    const int aRow = wm * 32 + (lane & 15);
    const int aCol = (lane >> 4) * 8;
    const int bRow = wn * 32 + ((lane >> 4) * 8) + (lane & 7);
    const int bCol = ((lane >> 3) & 1) * 8;

    for (int t = 0; t < ktiles; ++t) {
        #pragma unroll
        for (int i = 0; i < 8; ++i) {
            const int idx = tid + i * 256;
            const int r = idx >> 4, cp = (idx & 15) * 2;
            const size_t go = (size_t)(m0 + r) * lda + t * 32 + cp;
            *reinterpret_cast<__nv_bfloat162*>(&sAH[r * SSTR + cp]) =
                *reinterpret_cast<const __nv_bfloat162*>(&Ah[go]);
            *reinterpret_cast<__nv_bfloat162*>(&sAL[r * SSTR + cp]) =
                *reinterpret_cast<const __nv_bfloat162*>(&Al[go]);
        }
        #pragma unroll
        for (int i = 0; i < 4; ++i) {
            const int idx = tid + i * 256;
            const int r = idx >> 4, cp = (idx & 15) * 2;
            const size_t go = (size_t)(n0 + r) * ldb + t * 32 + cp;
            *reinterpret_cast<__nv_bfloat162*>(&sBH[r * SSTR + cp]) =
                *reinterpret_cast<const __nv_bfloat162*>(&Bh[go]);
            *reinterpret_cast<__nv_bfloat162*>(&sBL[r * SSTR + cp]) =
                *reinterpret_cast<const __nv_bfloat162*>(&Bl[go]);
        }
        __syncthreads();

        #pragma unroll
        for (int kk = 0; kk < 2; ++kk) {
            uint32_t ah[2][4], al[2][4], bh[2][4], bl[2][4];
            #pragma unroll
            for (int mt = 0; mt < 2; ++mt) {
                const uint32_t off = (uint32_t)(((aRow + mt * 16) * SSTR + kk * 16 + aCol) * 2);
                ldm_x4(aBH + off, ah[mt]);
                ldm_x4(aBL + off, al[mt]);
            }
            #pragma unroll
            for (int nt2 = 0; nt2 < 2; ++nt2) {
                const uint32_t off = (uint32_t)(((bRow + nt2 * 16) * SSTR + kk * 16 + bCol) * 2);
                ldm_x4(bBH + off, bh[nt2]);
                ldm_x4(bBL + off, bl[nt2]);
            }
            #pragma unroll
            for (int mt = 0; mt < 2; ++mt)
                #pragma unroll
                for (int nt = 0; nt < 4; ++nt) {
                    const uint32_t* fh = &bh[nt >> 1][(nt & 1) * 2];
                    const uint32_t* fl = &bl[nt >> 1][(nt & 1) * 2];
                    mma_bf16(acc[mt][nt], ah[mt], fh);
                    mma_bf16(acc[mt][nt], al[mt], fh);
                    mma_bf16(acc[mt][nt], ah[mt], fl);
                }
        }
        __syncthreads();
    }

    // epilogue
    #pragma unroll
    for (int mt = 0; mt < 2; ++mt) {
        const int row0 = m0 + wm * 32 + mt * 16 + (lane >> 2);
        #pragma unroll
        for (int nt = 0; nt < 4; ++nt) {
            const int col = n0 + wn * 32 + nt * 8 + (lane & 3) * 2;
            const float* d = acc[mt][nt];
            #pragma unroll
            for (int rr = 0; rr < 2; ++rr) {
                const int row = row0 + rr * 8;
                if (EPI == 0) {
                    __nv_bfloat16 hh[2], ll[2];
                    #pragma unroll
                    for (int q = 0; q < 2; ++q) {
                        const int c = col + q;
                        float y = d[rr * 2 + q] + __ldg(bias + c);
                        float z = 0.0f;
                        #pragma unroll
                        for (int l = 0; l < 4; ++l) {
                            const int idx = l * HIDD + c;
                            const float s = __ldg(bn_gamma + idx) * rsqrtf(__ldg(bn_var + idx) + 1e-5f);
                            const float sh = __ldg(bn_beta + idx) - __ldg(bn_mean + idx) * s;
                            y = fmaxf(fmaf(y, s, sh), 0.0f);
                            z = fmaxf(z, y);
                        }
                        bf16_split(z, hh[q], ll[q]);
                    }
                    __nv_bfloat162 th; th.x = hh[0]; th.y = hh[1];
                    __nv_bfloat162 tl; tl.x = ll[0]; tl.y = ll[1];
                    *reinterpret_cast<__nv_bfloat162*>(&Ch[(size_t)row * ldc + col]) = th;
                    *reinterpret_cast<__nv_bfloat162*>(&Cl[(size_t)row * ldc + col]) = tl;
                } else {
                    float2 o;
                    o.x = fmaxf(d[rr * 2 + 0] + __ldg(bias + col + 0), 0.0f);
                    o.y = fmaxf(d[rr * 2 + 1] + __ldg(bias + col + 1), 0.0f);
                    *reinterpret_cast<float2*>(&Cf[(size_t)row * ldc + col]) = o;
                }
            }
        }
    }
}

// ---------------- kernel 5: lin2 + log_softmax ----------------
__global__ void lin2_lsm(const float* __restrict__ Z2, const float* __restrict__ W2,
                         const float* __restrict__ b2, float* __restrict__ out) {
    const int gw   = (blockIdx.x * blockDim.x + threadIdx.x) >> 5;
    const int lane = threadIdx.x & 31;
    if (gw >= BATCH) return;
    const float* zr = Z2 + (size_t)gw * HIDD;
    float z[8];
    #pragma unroll
    for (int j = 0; j < 8; ++j) z[j] = zr[lane + 32 * j];

    float logit[NOUT];
    #pragma unroll
    for (int o = 0; o < NOUT; ++o) {
        float p = 0.0f;
        #pragma unroll
        for (int j = 0; j < 8; ++j) p += z[j] * __ldg(W2 + o * HIDD + lane + 32 * j);
        #pragma unroll
        for (int off = 16; off; off >>= 1) p += __shfl_xor_sync(0xffffffffu, p, off);
        logit[o] = p + __ldg(b2 + o);
    }
    float m = logit[0];
    #pragma unroll
    for (int o = 1; o < NOUT; ++o) m = fmaxf(m, logit[o]);
    float s = 0.0f;
    #pragma unroll
    for (int o = 0; o < NOUT; ++o) s += expf(logit[o] - m);
    const float lse = m + logf(s);
    if (lane < NOUT) out[(size_t)gw * NOUT + lane] = logit[lane] - lse;
}

// ---------------- launcher ----------------
extern "C" void kernel_launch(void* const* d_in, const int* in_sizes, int n_in,
                              void* d_out, int out_size) {
    const float* x        = (const float*)d_in[0];
    const float* L        = (const float*)d_in[1];
    const float* lmax     = (const float*)d_in[2];
    const float* cl1W     = (const float*)d_in[3];
    const float* cl1b     = (const float*)d_in[4];
    const float* fc1W     = (const float*)d_in[5];
    const float* fc1b     = (const float*)d_in[6];
    const float* bn_gamma = (const float*)d_in[7];
    const float* bn_beta  = (const float*)d_in[8];
    const float* bn_mean  = (const float*)d_in[9];
    const float* bn_var   = (const float*)d_in[10];
    const float* lin1W    = (const float*)d_in[11];
    const float* lin1b    = (const float*)d_in[12];
    const float* lin2W    = (const float*)d_in[13];
    const float* lin2b    = (const float*)d_in[14];
    float* out = (float*)d_out;

    __nv_bfloat16 *pPh, *pPl, *pF1h, *pF1l, *pL1h, *pL1l, *pZ1h, *pZ1l;
    float* pZ2;
    cudaGetSymbolAddress((void**)&pPh,  g_poolh);
    cudaGetSymbolAddress((void**)&pPl,  g_pooll);
    cudaGetSymbolAddress((void**)&pF1h, g_fc1h);
    cudaGetSymbolAddress((void**)&pF1l, g_fc1l);
    cudaGetSymbolAddress((void**)&pL1h, g_lin1h);
    cudaGetSymbolAddress((void**)&pL1l, g_lin1l);
    cudaGetSymbolAddress((void**)&pZ1h, g_z1h);
    cudaGetSymbolAddress((void**)&pZ1l, g_z1l);
    cudaGetSymbolAddress((void**)&pZ2,  g_z2);

    // 1) prep: ELL + sort + rotated transpose + weight conversion
    build_ell<<<(NV * 32 + 255) / 256, 256>>>(L, lmax);
    sort_nodes<<<1, 1024>>>();
    transpose_ell<<<NSLOT / 256, 256>>>();
    conv_weights<<<(HIDD * 625 + 255) / 256, 256>>>(fc1W, lin1W);

    // 2) fused chebyshev + cl1 + relu + maxpool -> bf16 hi/lo pool
    const int smem = (2 * CHEBK * PLANE + 32) * (int)sizeof(float);  // 160128 B
    cudaFuncSetAttribute(cheby_fused, cudaFuncAttributeMaxDynamicSharedMemorySize, smem);
    cheby_fused<<<BATCH / BT, 1024, smem>>>(x, cl1W, cl1b);

    // 3) fc1 + BN x4 + relu + JK-max  (M=8192, N=256, K=640 padded), mma.sync bf16-split
    dim3 grid(HIDD / 64, BATCH / 128);   // (4, 64) = 256 CTAs
    gemm_mma<0><<<grid, 256>>>(pPh, pPl, KPAD, pF1h, pF1l, KPAD, KPAD / 32,
                               fc1b, bn_gamma, bn_beta, bn_mean, bn_var,
                               nullptr, pZ1h, pZ1l, HIDD);

    // 4) lin1 + relu  (M=8192, N=256, K=256)
    gemm_mma<1><<<grid, 256>>>(pZ1h, pZ1l, HIDD, pL1h, pL1l, HIDD, HIDD / 32,
                               lin1b, nullptr, nullptr, nullptr, nullptr,
                               pZ2, nullptr, nullptr, HIDD);

    // 5) lin2 + log_softmax
    lin2_lsm<<<BATCH / 8, 256>>>(pZ2, lin2W, lin2b, out);
}

// round 15
// speedup vs baseline: 2.0294x; 1.0143x over previous
#include <cuda_runtime.h>
#include <cuda_bf16.h>
#include <cstdint>

#define BATCH 8192
#define NV    1000
#define CHEBK 5
#define NF    5
#define HIDD  256
#define NOUT  10
#define KPAD  640
#define MAXW  32
#define BT    8
#define HBT   4
#define NSLOT 1024
#define PLANE (NV * HBT)

// ---------------- scratch ----------------
__device__ int2  g_ell[NV * MAXW];
__device__ int   g_ell_len[NV];
__device__ int   g_perm[NV];
__device__ int2  g_ellT[(NSLOT / 32) * MAXW * 32];
__device__ __nv_bfloat16 g_poolh[(size_t)BATCH * KPAD];   // pads (625..639) stay 0
__device__ __nv_bfloat16 g_pooll[(size_t)BATCH * KPAD];
__device__ __nv_bfloat16 g_fc1h[HIDD * KPAD];
__device__ __nv_bfloat16 g_fc1l[HIDD * KPAD];
__device__ __nv_bfloat16 g_lin1h[HIDD * HIDD];
__device__ __nv_bfloat16 g_lin1l[HIDD * HIDD];
__device__ __nv_bfloat16 g_z1h[(size_t)BATCH * HIDD];
__device__ __nv_bfloat16 g_z1l[(size_t)BATCH * HIDD];
__device__ float g_z2[(size_t)BATCH * HIDD];

// ---------------- helpers ----------------
__device__ __forceinline__ uint32_t smem_u32(const void* p) {
    uint32_t a;
    asm("{ .reg .u64 t; cvta.to.shared.u64 t, %1; cvt.u32.u64 %0, t; }" : "=r"(a) : "l"(p));
    return a;
}
__device__ __forceinline__ void bf16_split(float x, __nv_bfloat16& h, __nv_bfloat16& l) {
    h = __float2bfloat16(x);
    l = __float2bfloat16(x - __bfloat162float(h));
}
__device__ __forceinline__ void ldm_x4(uint32_t addr, uint32_t* r) {
    asm volatile("ldmatrix.sync.aligned.m8n8.x4.shared.b16 {%0,%1,%2,%3}, [%4];"
                 : "=r"(r[0]), "=r"(r[1]), "=r"(r[2]), "=r"(r[3]) : "r"(addr));
}
__device__ __forceinline__ void mma_bf16(float* d, const uint32_t* a, const uint32_t* b) {
    asm volatile("mma.sync.aligned.m16n8k16.row.col.f32.bf16.bf16.f32 "
                 "{%0,%1,%2,%3}, {%4,%5,%6,%7}, {%8,%9}, {%0,%1,%2,%3};"
                 : "+f"(d[0]), "+f"(d[1]), "+f"(d[2]), "+f"(d[3])
                 : "r"(a[0]), "r"(a[1]), "r"(a[2]), "r"(a[3]), "r"(b[0]), "r"(b[1]));
}
#define CP16(dst, src) \
    asm volatile("cp.async.ca.shared.global [%0], [%1], 16;" :: "r"(dst), "l"(src))
#define CP_COMMIT() asm volatile("cp.async.commit_group;")
#define CP_WAIT1()  asm volatile("cp.async.wait_group 1;")
#define CP_WAIT0()  asm volatile("cp.async.wait_group 0;")

// ---------------- kernel 1: build ELL of Lr = 2*L/lmax - I (warp/row) ----------------
__global__ void build_ell(const float* __restrict__ L, const float* __restrict__ lmax) {
    const int warp = (blockIdx.x * blockDim.x + threadIdx.x) >> 5;
    const int lane = threadIdx.x & 31;
    if (warp >= NV) return;
    const int v = warp;
    const float inv = 2.0f / lmax[0];
    int cnt = 0;
    #pragma unroll 4
    for (int c = 0; c < (NV + 31) / 32; ++c) {
        const int u = c * 32 + lane;
        float val = 0.0f;
        if (u < NV) val = L[(size_t)v * NV + u] * inv - (u == v ? 1.0f : 0.0f);
        const bool nz = (val != 0.0f);
        const unsigned m = __ballot_sync(0xffffffffu, nz);
        if (nz) {
            const int idx = cnt + __popc(m & ((1u << lane) - 1u));
            if (idx < MAXW) g_ell[v * MAXW + idx] = make_int2(u, __float_as_int(val));
        }
        cnt += __popc(m);
    }
    if (lane == 0) g_ell_len[v] = cnt < MAXW ? cnt : MAXW;
}

// ---------------- kernel 1b: deterministic rank sort (smem staged) ----------------
__global__ void sort_nodes() {
    __shared__ int sl[NV];
    const int tid = threadIdx.x;
    if (tid < NV) sl[tid] = g_ell_len[tid];
    __syncthreads();
    if (tid < NV) {
        const int len = sl[tid];
        int pos = 0;
        for (int u = 0; u < NV; ++u) {
            const int lu = sl[u];
            pos += (lu < len) || (lu == len && u < tid);
        }
        g_perm[pos] = tid;
    }
}

// ---------------- kernel 1c: lane-major transpose, rotated-class order ----------------
__global__ void transpose_ell() {
    const int s = blockIdx.x * blockDim.x + threadIdx.x;
    if (s >= NSLOT) return;
    const int grp = s >> 5, lane = s & 31;
    const int r = lane & 7;
    int v = -1, len = 0;
    if (s < NV) { v = g_perm[s]; len = g_ell_len[v]; }
    int2* dst = g_ellT + grp * (MAXW * 32) + lane;
    int jo = 0;
    for (int cc = 0; cc < 8; ++cc) {
        for (int j = 0; j < len; ++j) {
            const int2 e = g_ell[v * MAXW + j];
            if ((((e.x & 7) - r) & 7) == cc) dst[(jo++) * 32] = e;
        }
    }
    for (; jo < MAXW; ++jo) dst[jo * 32] = make_int2(0, 0);
}

// ---------------- kernel 1d: weight conversion to bf16 hi/lo ----------------
__global__ void conv_weights(const float* __restrict__ fc1W, const float* __restrict__ lin1W) {
    const int i = blockIdx.x * blockDim.x + threadIdx.x;
    if (i < HIDD * 625) {
        const int n = i / 625, k = i - n * 625;
        __nv_bfloat16 h, l;
        bf16_split(fc1W[i], h, l);
        g_fc1h[n * KPAD + k] = h;
        g_fc1l[n * KPAD + k] = l;
    }
    if (i < HIDD * HIDD) {
        __nv_bfloat16 h, l;
        bf16_split(lin1W[i], h, l);
        g_lin1h[i] = h;
        g_lin1l[i] = l;
    }
}

// ---------------- kernel 2: fused cheby + cl1 + relu + maxpool -> bf16 hi/lo ----------
__global__ __launch_bounds__(1024, 1)
void cheby_fused(const float* __restrict__ x,
                 const float* __restrict__ W,
                 const float* __restrict__ bias) {
    extern __shared__ float sT[];
    float* sLo = sT;
    float* sHi = sT + CHEBK * PLANE;
    float* sW  = sT + 2 * CHEBK * PLANE;
    const int b0  = blockIdx.x * BT;
    const int tid = threadIdx.x;

    if (tid < NF * CHEBK) sW[tid] = W[tid];
    if (tid < NF) sW[NF * CHEBK + tid] = bias[tid];

    #pragma unroll
    for (int i = tid; i < NV * BT; i += 1024) {
        const int bb = i / NV, v = i - bb * NV;
        const float val = x[(size_t)(b0 + bb) * NV + v];
        if (bb < HBT) sLo[v * HBT + bb] = val;
        else          sHi[v * HBT + (bb - HBT)] = val;
    }
    __syncthreads();

    const int slot = tid;
    const int grp  = tid >> 5, lane = tid & 31;
    int v = 0, len = 0;
    if (slot < NV) { v = g_perm[slot]; len = g_ell_len[v]; }
    const int lm = __reduce_max_sync(0xffffffffu, len);
    const int2* __restrict__ ep = g_ellT + grp * (MAXW * 32) + lane;

    #pragma unroll
    for (int k = 1; k < CHEBK; ++k) {
        const float* __restrict__ Lo1 = sLo + (k - 1) * PLANE;
        const float* __restrict__ Hi1 = sHi + (k - 1) * PLANE;
        float4 A0 = make_float4(0.f, 0.f, 0.f, 0.f);
        float4 A1 = make_float4(0.f, 0.f, 0.f, 0.f);
        #pragma unroll 2
        for (int j = 0; j < lm; ++j) {
            const int2 e = __ldg(&ep[j * 32]);
            const float w = __int_as_float(e.y);
            const float4 t0 = *reinterpret_cast<const float4*>(Lo1 + e.x * HBT);
            const float4 t1 = *reinterpret_cast<const float4*>(Hi1 + e.x * HBT);
            A0.x = fmaf(w, t0.x, A0.x); A0.y = fmaf(w, t0.y, A0.y);
            A0.z = fmaf(w, t0.z, A0.z); A0.w = fmaf(w, t0.w, A0.w);
            A1.x = fmaf(w, t1.x, A1.x); A1.y = fmaf(w, t1.y, A1.y);
            A1.z = fmaf(w, t1.z, A1.z); A1.w = fmaf(w, t1.w, A1.w);
        }
        if (slot < NV) {
            float4* toL = reinterpret_cast<float4*>(sLo + k * PLANE + v * HBT);
            float4* toH = reinterpret_cast<float4*>(sHi + k * PLANE + v * HBT);
            if (k == 1) {
                *toL = A0; *toH = A1;
            } else {
                const float4 ma = *reinterpret_cast<const float4*>(sLo + (k - 2) * PLANE + v * HBT);
                const float4 mb = *reinterpret_cast<const float4*>(sHi + (k - 2) * PLANE + v * HBT);
                *toL = make_float4(2.f * A0.x - ma.x, 2.f * A0.y - ma.y,
                                   2.f * A0.z - ma.z, 2.f * A0.w - ma.w);
                *toH = make_float4(2.f * A1.x - mb.x, 2.f * A1.y - mb.y,
                                   2.f * A1.z - mb.z, 2.f * A1.w - mb.w);
            }
        }
        __syncthreads();
    }

    if (tid < 125 * BT) {
        const int bb = tid & (BT - 1);
        const int g  = tid / BT;
        const float* base = (bb < HBT) ? sLo : sHi;
        const int bo = bb & (HBT - 1);
        float m[NF];
        #pragma unroll
        for (int f = 0; f < NF; ++f) m[f] = -3.4e38f;
        #pragma unroll
        for (int vi = 0; vi < 8; ++vi) {
            const int vv = g * 8 + vi;
            float t[CHEBK];
            #pragma unroll
            for (int k = 0; k < CHEBK; ++k) t[k] = base[k * PLANE + vv * HBT + bo];
            #pragma unroll
            for (int f = 0; f < NF; ++f) {
                float s = sW[NF * CHEBK + f];
                #pragma unroll
                for (int k = 0; k < CHEBK; ++k) s = fmaf(sW[f * CHEBK + k], t[k], s);
                m[f] = fmaxf(m[f], s);
            }
        }
        const size_t op = (size_t)(b0 + bb) * KPAD + g * NF;
        #pragma unroll
        for (int f = 0; f < NF; ++f) {
            __nv_bfloat16 h, l;
            bf16_split(fmaxf(m[f], 0.0f), h, l);
            g_poolh[op + f] = h;
            g_pooll[op + f] = l;
        }
    }
}

// ---------------- kernels 3/4: cp.async double-buffered mma.sync bf16-split GEMM ------
// CTA tile 128x64, 8 warps (4x2), warp tile 32x32 (2x4 m16n8k16 frags), 3 passes.
// Dynamic smem: 2 stages x (AH 10240 | AL 10240 | BH 5120 | BL 5120) B + 576 fp coeffs.
#define STG   30720
#define O_AL  10240
#define O_BH  20480
#define O_BL  25600
#define O_EP  61440
#define GSM_TOT (O_EP + 576 * 4)

template <int EPI>
__global__ __launch_bounds__(256, 2)
void gemm_mma(const __nv_bfloat16* __restrict__ Ah, const __nv_bfloat16* __restrict__ Al,
              int lda,
              const __nv_bfloat16* __restrict__ Bh, const __nv_bfloat16* __restrict__ Bl,
              int ldb, int ktiles,
              const float* __restrict__ bias,
              const float* __restrict__ bn_gamma, const float* __restrict__ bn_beta,
              const float* __restrict__ bn_mean,  const float* __restrict__ bn_var,
              float* __restrict__ Cf,
              __nv_bfloat16* __restrict__ Ch, __nv_bfloat16* __restrict__ Cl, int ldc) {
    extern __shared__ char sm[];
    const uint32_t sbase = smem_u32(sm);

    const int tid = threadIdx.x, wid = tid >> 5, lane = tid & 31;
    const int wm = wid >> 1, wn = wid & 1;
    const int m0 = blockIdx.y * 128, n0 = blockIdx.x * 64;

    float acc[2][4][4];
    #pragma unroll
    for (int a = 0; a < 2; ++a)
        #pragma unroll
        for (int b = 0; b < 4; ++b)
            #pragma unroll
            for (int c = 0; c < 4; ++c) acc[a][b][c] = 0.0f;

    // loader: 6 x 16B chunks per thread per tile (A: 2x512 chunks, B: 2x256)
    const int aRowL = tid >> 2, aOffL = (tid & 3) * 16;          // +i*64 rows
    auto load_tile = [&](int t, int stage) {
        const uint32_t sb = sbase + stage * STG;
        #pragma unroll
        for (int i = 0; i < 2; ++i) {
            const int row = aRowL + i * 64;
            const uint32_t dst = sb + row * 80 + aOffL;
            const size_t go = (size_t)(m0 + row) * lda + t * 32 + (aOffL >> 1);
            CP16(dst, Ah + go);
            CP16(dst + O_AL, Al + go);
        }
        {
            const int row = tid >> 2;
            const uint32_t dst = sb + O_BH + row * 80 + aOffL;
            const size_t go = (size_t)(n0 + row) * ldb + t * 32 + (aOffL >> 1);
            CP16(dst, Bh + go);
            CP16(dst + (O_BL - O_BH), Bl + go);
        }
        CP_COMMIT();
    };

    const int aRow = wm * 32 + (lane & 15);
    const int aCol = (lane >> 4) * 8;
    const int bRow = wn * 32 + ((lane >> 4) * 8) + (lane & 7);
    const int bCol = ((lane >> 3) & 1) * 8;

    load_tile(0, 0);
    int stage = 0;
    for (int t = 0; t < ktiles; ++t) {
        if (t + 1 < ktiles) {
            load_tile(t + 1, stage ^ 1);
            CP_WAIT1();
        } else {
            CP_WAIT0();
        }
        __syncthreads();

        const uint32_t sb = sbase + stage * STG;
        #pragma unroll
        for (int kk = 0; kk < 2; ++kk) {
            uint32_t ah[2][4], al[2][4], bh[2][4], bl[2][4];
            #pragma unroll
            for (int mt = 0; mt < 2; ++mt) {
                const uint32_t off = (uint32_t)((aRow + mt * 16) * 80 + (kk * 16 + aCol) * 2);
                ldm_x4(sb + off, ah[mt]);
                ldm_x4(sb + O_AL + off, al[mt]);
            }
            #pragma unroll
            for (int nt2 = 0; nt2 < 2; ++nt2) {
                const uint32_t off = (uint32_t)((bRow + nt2 * 16) * 80 + (kk * 16 + bCol) * 2);
                ldm_x4(sb + O_BH + off, bh[nt2]);
                ldm_x4(sb + O_BL + off, bl[nt2]);
            }
            #pragma unroll
            for (int mt = 0; mt < 2; ++mt)
                #pragma unroll
                for (int nt = 0; nt < 4; ++nt) {
                    const uint32_t* fh = &bh[nt >> 1][(nt & 1) * 2];
                    const uint32_t* fl = &bl[nt >> 1][(nt & 1) * 2];
                    mma_bf16(acc[mt][nt], ah[mt], fh);
                    mma_bf16(acc[mt][nt], al[mt], fh);
                    mma_bf16(acc[mt][nt], ah[mt], fl);
                }
        }
        __syncthreads();
        stage ^= 1;
    }

    // stage epilogue coefficients once per CTA
    float* sEp = reinterpret_cast<float*>(sm + O_EP);  // [0:64) bias, [64:320) sc, [320:576) sh
    if (tid < 64) {
        const int col = n0 + tid;
        sEp[tid] = __ldg(bias + col);
        if (EPI == 0) {
            #pragma unroll
            for (int l = 0; l < 4; ++l) {
                const int idx = l * HIDD + col;
                const float s = __ldg(bn_gamma + idx) * rsqrtf(__ldg(bn_var + idx) + 1e-5f);
                sEp[64 + l * 64 + tid]  = s;
                sEp[320 + l * 64 + tid] = __ldg(bn_beta + idx) - __ldg(bn_mean + idx) * s;
            }
        }
    }
    __syncthreads();

    #pragma unroll
    for (int mt = 0; mt < 2; ++mt) {
        const int row0 = m0 + wm * 32 + mt * 16 + (lane >> 2);
        #pragma unroll
        for (int nt = 0; nt < 4; ++nt) {
            const int cl = wn * 32 + nt * 8 + (lane & 3) * 2;  // local col in [0,64)
            const int col = n0 + cl;
            const float* d = acc[mt][nt];
            #pragma unroll
            for (int rr = 0; rr < 2; ++rr) {
                const int row = row0 + rr * 8;
                if (EPI == 0) {
                    __nv_bfloat16 hh[2], ll[2];
                    #pragma unroll
                    for (int q = 0; q < 2; ++q) {
                        float y = d[rr * 2 + q] + sEp[cl + q];
                        float z = 0.0f;
                        #pragma unroll
                        for (int l = 0; l < 4; ++l) {
                            y = fmaxf(fmaf(y, sEp[64 + l * 64 + cl + q],
                                           sEp[320 + l * 64 + cl + q]), 0.0f);
                            z = fmaxf(z, y);
                        }
                        bf16_split(z, hh[q], ll[q]);
                    }
                    __nv_bfloat162 th; th.x = hh[0]; th.y = hh[1];
                    __nv_bfloat162 tl; tl.x = ll[0]; tl.y = ll[1];
                    *reinterpret_cast<__nv_bfloat162*>(&Ch[(size_t)row * ldc + col]) = th;
                    *reinterpret_cast<__nv_bfloat162*>(&Cl[(size_t)row * ldc + col]) = tl;
                } else {
                    float2 o;
                    o.x = fmaxf(d[rr * 2 + 0] + sEp[cl + 0], 0.0f);
                    o.y = fmaxf(d[rr * 2 + 1] + sEp[cl + 1], 0.0f);
                    *reinterpret_cast<float2*>(&Cf[(size_t)row * ldc + col]) = o;
                }
            }
        }
    }
}

// ---------------- kernel 5: lin2 + log_softmax ----------------
__global__ void lin2_lsm(const float* __restrict__ Z2, const float* __restrict__ W2,
                         const float* __restrict__ b2, float* __restrict__ out) {
    const int gw   = (blockIdx.x * blockDim.x + threadIdx.x) >> 5;
    const int lane = threadIdx.x & 31;
    if (gw >= BATCH) return;
    const float* zr = Z2 + (size_t)gw * HIDD;
    float z[8];
    #pragma unroll
    for (int j = 0; j < 8; ++j) z[j] = zr[lane + 32 * j];

    float logit[NOUT];
    #pragma unroll
    for (int o = 0; o < NOUT; ++o) {
        float p = 0.0f;
        #pragma unroll
        for (int j = 0; j < 8; ++j) p += z[j] * __ldg(W2 + o * HIDD + lane + 32 * j);
        #pragma unroll
        for (int off = 16; off; off >>= 1) p += __shfl_xor_sync(0xffffffffu, p, off);
        logit[o] = p + __ldg(b2 + o);
    }
    float m = logit[0];
    #pragma unroll
    for (int o = 1; o < NOUT; ++o) m = fmaxf(m, logit[o]);
    float s = 0.0f;
    #pragma unroll
    for (int o = 0; o < NOUT; ++o) s += expf(logit[o] - m);
    const float lse = m + logf(s);
    if (lane < NOUT) out[(size_t)gw * NOUT + lane] = logit[lane] - lse;
}

// ---------------- launcher ----------------
extern "C" void kernel_launch(void* const* d_in, const int* in_sizes, int n_in,
                              void* d_out, int out_size) {
    const float* x        = (const float*)d_in[0];
    const float* L        = (const float*)d_in[1];
    const float* lmax     = (const float*)d_in[2];
    const float* cl1W     = (const float*)d_in[3];
    const float* cl1b     = (const float*)d_in[4];
    const float* fc1W     = (const float*)d_in[5];
    const float* fc1b     = (const float*)d_in[6];
    const float* bn_gamma = (const float*)d_in[7];
    const float* bn_beta  = (const float*)d_in[8];
    const float* bn_mean  = (const float*)d_in[9];
    const float* bn_var   = (const float*)d_in[10];
    const float* lin1W    = (const float*)d_in[11];
    const float* lin1b    = (const float*)d_in[12];
    const float* lin2W    = (const float*)d_in[13];
    const float* lin2b    = (const float*)d_in[14];
    float* out = (float*)d_out;

    __nv_bfloat16 *pPh, *pPl, *pF1h, *pF1l, *pL1h, *pL1l, *pZ1h, *pZ1l;
    float* pZ2;
    cudaGetSymbolAddress((void**)&pPh,  g_poolh);
    cudaGetSymbolAddress((void**)&pPl,  g_pooll);
    cudaGetSymbolAddress((void**)&pF1h, g_fc1h);
    cudaGetSymbolAddress((void**)&pF1l, g_fc1l);
    cudaGetSymbolAddress((void**)&pL1h, g_lin1h);
    cudaGetSymbolAddress((void**)&pL1l, g_lin1l);
    cudaGetSymbolAddress((void**)&pZ1h, g_z1h);
    cudaGetSymbolAddress((void**)&pZ1l, g_z1l);
    cudaGetSymbolAddress((void**)&pZ2,  g_z2);

    // 1) prep
    build_ell<<<(NV * 32 + 255) / 256, 256>>>(L, lmax);
    sort_nodes<<<1, 1024>>>();
    transpose_ell<<<NSLOT / 256, 256>>>();
    conv_weights<<<(HIDD * 625 + 255) / 256, 256>>>(fc1W, lin1W);

    // 2) fused chebyshev + cl1 + relu + maxpool -> bf16 hi/lo pool
    const int smem = (2 * CHEBK * PLANE + 32) * (int)sizeof(float);  // 160128 B
    cudaFuncSetAttribute(cheby_fused, cudaFuncAttributeMaxDynamicSharedMemorySize, smem);
    cheby_fused<<<BATCH / BT, 1024, smem>>>(x, cl1W, cl1b);

    // 3) fc1 + BN x4 + relu + JK-max  (K=640 padded), double-buffered mma.sync
    cudaFuncSetAttribute(gemm_mma<0>, cudaFuncAttributeMaxDynamicSharedMemorySize, GSM_TOT);
    cudaFuncSetAttribute(gemm_mma<1>, cudaFuncAttributeMaxDynamicSharedMemorySize, GSM_TOT);
    dim3 grid(HIDD / 64, BATCH / 128);   // (4, 64) = 256 CTAs
    gemm_mma<0><<<grid, 256, GSM_TOT>>>(pPh, pPl, KPAD, pF1h, pF1l, KPAD, KPAD / 32,
                                        fc1b, bn_gamma, bn_beta, bn_mean, bn_var,
                                        nullptr, pZ1h, pZ1l, HIDD);

    // 4) lin1 + relu  (K=256)
    gemm_mma<1><<<grid, 256, GSM_TOT>>>(pZ1h, pZ1l, HIDD, pL1h, pL1l, HIDD, HIDD / 32,
                                        lin1b, nullptr, nullptr, nullptr, nullptr,
                                        pZ2, nullptr, nullptr, HIDD);

    // 5) lin2 + log_softmax
    lin2_lsm<<<BATCH / 8, 256>>>(pZ2, lin2W, lin2b, out);
}